// round 1
// baseline (speedup 1.0000x reference)
#include <cuda_runtime.h>
#include <cuda_bf16.h>

#define NN 100000
#define NE 1600000
#define DD 128
#define LL 3

// ---------------- device scratch (static allocation, allowed) ----------------
__device__ float g_h[(size_t)NN * DD];   // current node features
__device__ float g_S[(size_t)NN * DD];   // (h + agg) * inv, GEMM input
__device__ float g_inv[NN];
__device__ int   g_deg[NN];
__device__ int   g_off[NN + 1];
__device__ int   g_cur[NN];
__device__ int   g_csr[NE];

// ---------------- setup: h = emb[annotation], zero deg ----------------
__global__ void k_init(const int* __restrict__ ann, const float* __restrict__ emb) {
    int t = blockIdx.x * blockDim.x + threadIdx.x;
    if (t < NN * 32) {
        int v = t >> 5, lane = t & 31;
        int a = ann[v];
        float4 val = ((const float4*)emb)[(size_t)a * 32 + lane];
        ((float4*)g_h)[t] = val;
    }
    if (t < NN) g_deg[t] = 0;
}

// ---------------- degree count ----------------
__global__ void k_count(const int* __restrict__ dst) {
    int e = blockIdx.x * blockDim.x + threadIdx.x;
    if (e < NE) atomicAdd(&g_deg[dst[e]], 1);
}

// ---------------- single-block exclusive scan of deg -> off, cur, inv ----------------
__global__ void k_scan() {
    __shared__ int sh[1024];
    __shared__ int s_carry;
    int tid = threadIdx.x;
    if (tid == 0) { s_carry = 0; g_off[0] = 0; }
    __syncthreads();
    for (int base = 0; base < NN; base += 1024) {
        int i = base + tid;
        int d = (i < NN) ? g_deg[i] : 0;
        sh[tid] = d;
        __syncthreads();
        // Hillis-Steele inclusive scan
        #pragma unroll
        for (int o = 1; o < 1024; o <<= 1) {
            int t = (tid >= o) ? sh[tid - o] : 0;
            __syncthreads();
            sh[tid] += t;
            __syncthreads();
        }
        int carry = s_carry;
        if (i < NN) {
            int incl = carry + sh[tid];
            g_off[i + 1] = incl;
            g_cur[i] = incl - d;          // exclusive prefix
            g_inv[i] = 1.0f / (float)(d + 1);
        }
        __syncthreads();
        if (tid == 1023) s_carry = carry + sh[1023];
        __syncthreads();
    }
}

// ---------------- scatter edges into CSR (grouped by dst) ----------------
__global__ void k_scatter(const int* __restrict__ src, const int* __restrict__ dst) {
    int e = blockIdx.x * blockDim.x + threadIdx.x;
    if (e < NE) {
        int d = dst[e];
        int p = atomicAdd(&g_cur[d], 1);
        g_csr[p] = src[e];
    }
}

// ---------------- SAGE aggregation: warp per node ----------------
__global__ void __launch_bounds__(256) k_sage() {
    int gt = blockIdx.x * blockDim.x + threadIdx.x;
    int v = gt >> 5;
    if (v >= NN) return;
    int lane = gt & 31;
    const float4* h4 = (const float4*)g_h;
    float4 acc = h4[(size_t)v * 32 + lane];    // self term
    int s = g_off[v], e = g_off[v + 1];
    for (int i = s; i < e; i++) {
        int u = g_csr[i];                       // broadcast read
        float4 x = h4[(size_t)u * 32 + lane];
        acc.x += x.x; acc.y += x.y; acc.z += x.z; acc.w += x.w;
    }
    float iv = g_inv[v];
    float4 r;
    r.x = acc.x * iv; r.y = acc.y * iv; r.z = acc.z * iv; r.w = acc.w * iv;
    ((float4*)g_S)[(size_t)v * 32 + lane] = r;
}

// ---------------- GEMM: out = relu(S @ W + b), 128x128 block tile ----------------
#define GPAD 132
#define GSMEM (2 * 128 * GPAD * 4)

__global__ void __launch_bounds__(256) k_gemm(const float* __restrict__ W,
                                              const float* __restrict__ bias,
                                              float* out_final) {
    extern __shared__ float sm[];
    float* As = sm;                // [128][GPAD] rows of S (row-major, k contiguous)
    float* Bs = sm + 128 * GPAD;   // [128][GPAD] W (k rows, n contiguous)
    int m0 = blockIdx.x * 128;
    int tid = threadIdx.x;         // 256 threads

    // cooperative load: 4096 float4 each for As and Bs
    #pragma unroll
    for (int t = 0; t < 16; t++) {
        int q = tid + t * 256;     // 0..4095
        int r = q >> 5, c4 = q & 31;
        float4 v;
        if (m0 + r < NN) v = ((const float4*)g_S)[(size_t)(m0 + r) * 32 + c4];
        else             v = make_float4(0.f, 0.f, 0.f, 0.f);
        *(float4*)&As[r * GPAD + c4 * 4] = v;
        *(float4*)&Bs[r * GPAD + c4 * 4] = ((const float4*)W)[q];
    }
    __syncthreads();

    int ty = tid >> 4, tx = tid & 15;
    float acc[8][8];
    #pragma unroll
    for (int i = 0; i < 8; i++)
        #pragma unroll
        for (int j = 0; j < 8; j++) acc[i][j] = 0.f;

    #pragma unroll 4
    for (int k = 0; k < 128; k++) {
        float a[8], b[8];
        float4 b0 = *(float4*)&Bs[k * GPAD + tx * 8];
        float4 b1 = *(float4*)&Bs[k * GPAD + tx * 8 + 4];
        b[0] = b0.x; b[1] = b0.y; b[2] = b0.z; b[3] = b0.w;
        b[4] = b1.x; b[5] = b1.y; b[6] = b1.z; b[7] = b1.w;
        #pragma unroll
        for (int i = 0; i < 8; i++) a[i] = As[(ty * 8 + i) * GPAD + k];
        #pragma unroll
        for (int i = 0; i < 8; i++)
            #pragma unroll
            for (int j = 0; j < 8; j++)
                acc[i][j] = fmaf(a[i], b[j], acc[i][j]);
    }

    float* out = out_final ? out_final : g_h;
    #pragma unroll
    for (int i = 0; i < 8; i++) {
        int m = m0 + ty * 8 + i;
        if (m < NN) {
            #pragma unroll
            for (int j = 0; j < 8; j += 4) {
                int c = tx * 8 + j;
                float4 r4;
                r4.x = fmaxf(acc[i][j + 0] + bias[c + 0], 0.f);
                r4.y = fmaxf(acc[i][j + 1] + bias[c + 1], 0.f);
                r4.z = fmaxf(acc[i][j + 2] + bias[c + 2], 0.f);
                r4.w = fmaxf(acc[i][j + 3] + bias[c + 3], 0.f);
                *(float4*)&out[(size_t)m * DD + c] = r4;
            }
        }
    }
}

// ---------------- launcher ----------------
extern "C" void kernel_launch(void* const* d_in, const int* in_sizes, int n_in,
                              void* d_out, int out_size) {
    const int*   ann = (const int*)d_in[0];
    const int*   src = (const int*)d_in[1];
    const int*   dst = (const int*)d_in[2];
    const float* emb = (const float*)d_in[3];
    const float* Ws  = (const float*)d_in[4];
    const float* bs  = (const float*)d_in[5];
    float*       out = (float*)d_out;

    cudaFuncSetAttribute(k_gemm, cudaFuncAttributeMaxDynamicSharedMemorySize, GSMEM);

    k_init   <<<(NN * 32 + 255) / 256, 256>>>(ann, emb);
    k_count  <<<(NE + 255) / 256, 256>>>(dst);
    k_scan   <<<1, 1024>>>();
    k_scatter<<<(NE + 255) / 256, 256>>>(src, dst);

    int gemm_grid = (NN + 127) / 128;  // 782
    for (int l = 0; l < LL; l++) {
        k_sage<<<(NN * 32 + 255) / 256, 256>>>();
        k_gemm<<<gemm_grid, 256, GSMEM>>>(Ws + (size_t)l * DD * DD,
                                          bs + (size_t)l * DD,
                                          (l == LL - 1) ? out : nullptr);
    }
}